// round 17
// baseline (speedup 1.0000x reference)
#include <cuda_runtime.h>
#include <math.h>

// Problem constants
#define BB 16
#define DD 16
#define HH 128
#define WW 160
#define W4 (WW/4)            // 40 float4 per (image,channel,row)
#define NCH 4                // channels per block
#define NT (NCH*W4)          // 160 threads = 5 warps
#define TH 16                // output rows per block
#define NCHUNK (HH/TH)       // 8
#define HW (HH*WW)
#define PL4 (HH*W4)          // float4 per channel plane
#define NV4 (BB*DD*PL4)

__device__ float4 g_x[2][NV4];    // x ping-pong, native (B,D,H,W) layout

__device__ __forceinline__ int clampr(int r) {
    return r < 0 ? 0 : (r > HH-1 ? HH-1 : r);
}

// -------------- fused TRIPLE Richardson step, 2 rows per epoch ------------
// Epoch i (i=0..11), l0 = h0-3+2i:
//   S0: load x rows l0, l0+1; publish x-edges            (i <= 10)
//   S1: x1 at rows l0-1, l0   (tau a); publish y-edges   (i <= 10)
//   S2: x2 at rows l0-3, l0-2 (tau b); publish p-edges   (i >= 2)
//   S3: x3 at rows l0-5, l0-4 (tau c); store             (i >= 4)
// One barrier per epoch (12 vs 24 in R15). Edge rings depth 8:
// within one barrier interval, x-edge reads rows l0-1,l0 vs next-S0 writes
// rows l0+2,l0+3 (distance <= 4 -> distinct mod 8); y: S1 writes l0-1,l0 vs
// S2 reads l0-3,l0-2; p: S2 writes l0-3,l0-2 vs S3 reads l0-5,l0-4 -- all
// distinct mod 8. Cross-epoch reads are separated by the barrier.
// FIFO carry (end-of-epoch, shift by 2):
//   x: xm2=xv0, xm1=xv1   (x rows l0, l0+1)
//   y: y2=y0, y1=ov0, y0=ov1   -> next epoch holds x1(l0-2), x1(l0-1), x1(l0)
//   z: zz2=zz0, zz1=pv0, zz0=pv1
//   b: bf1=bnew0, bf0=bnew1
// Pseudo-rows (clamped) only reach stored rows via wy weights that are
// exactly zero at domain edges (same argument as R12..R15).
template<int SAME_XB>
__global__ void __launch_bounds__(NT, 4)
rich_tri2(const float4* __restrict__ x_in,
          const float4* __restrict__ b_in,
          const float*  __restrict__ wxy,
          float4* __restrict__ x_out,
          float ta, float tb, float tc)
{
    __shared__ float xlo[8][NT], xhi[8][NT];
    __shared__ float ylo[8][NT], yhi[8][NT];
    __shared__ float plo[8][NT], phi[8][NT];

    const int t  = threadIdx.x;        // 160
    const int ch = t / W4;             // 0..3
    const int wb = t - ch*W4;
    const int blk = blockIdx.x;
    const int cg  = blk & 3;
    const int r2  = blk >> 2;
    const int bi  = r2 >> 3;
    const int h0  = (r2 & 7) << 4;     // chunk*TH

    const size_t cb = ((size_t)(bi*DD + cg*NCH + ch))*PL4 + wb;
    const float* wxb = wxy + (size_t)bi*2*HW + wb*4;
    const float* wyb = wxb + HW;
    const int tm = t > 0 ? t-1 : 0;
    const int tp = t < NT-1 ? t+1 : NT-1;
    const float4 z = {0.f,0.f,0.f,0.f};

    auto stage = [&](int j, float4 c, float4 u, float4 d,
                     float lw, float rx, float4 bv, float tau) -> float4 {
        const int jc = clampr(j);
        const float* wxr = wxb + jc*WW;
        float4 wxv = *(const float4*)wxr;
        float  wxl = (wb > 0) ? wxr[-1] : 0.f;
        if (wb == W4-1) wxv.w = 0.f;
        float4 wyd = *(const float4*)(wyb + jc*WW);
        float4 wyu = *(const float4*)(wyb + clampr(j-1)*WW);
        if (j <= 0)     wyu = z;
        if (j >= HH-1)  wyd = z;

        float hxm = wxl   * (c.x - lw);
        float hx0 = wxv.x * (c.y - c.x);
        float hx1 = wxv.y * (c.z - c.y);
        float hx2 = wxv.z * (c.w - c.z);
        float hx3 = wxv.w * (rx  - c.w);

        float4 lap;
        lap.x = (hxm - hx0) + wyu.x*(c.x - u.x) - wyd.x*(d.x - c.x);
        lap.y = (hx0 - hx1) + wyu.y*(c.y - u.y) - wyd.y*(d.y - c.y);
        lap.z = (hx1 - hx2) + wyu.z*(c.z - u.z) - wyd.z*(d.z - c.z);
        lap.w = (hx2 - hx3) + wyu.w*(c.w - u.w) - wyd.w*(d.w - c.w);

        float4 o;
        o.x = c.x + tau*(bv.x - c.x - lap.x);
        o.y = c.y + tau*(bv.y - c.y - lap.y);
        o.z = c.z + tau*(bv.z - c.z - lap.z);
        o.w = c.w + tau*(bv.w - c.w - lap.w);
        return o;
    };

    // FIFOs
    float4 xm2 = z, xm1 = z;
    float4 y0 = z, y1 = z, y2 = z;
    float4 zz0 = z, zz1 = z, zz2 = z;
    float4 bf0 = z, bf1 = z;

    #pragma unroll 4
    for (int i = 0; i < 12; ++i) {
        const int l0 = h0 - 3 + 2*i;

        // ---- S0: load and publish x rows l0, l0+1
        float4 xv0 = z, xv1 = z;
        if (i <= 10) {
            xv0 = x_in[cb + (size_t)clampr(l0  )*W4];
            xv1 = x_in[cb + (size_t)clampr(l0+1)*W4];
            xlo[ l0    & 7][t] = xv0.x;  xhi[ l0    & 7][t] = xv0.w;
            xlo[(l0+1) & 7][t] = xv1.x;  xhi[(l0+1) & 7][t] = xv1.w;
        }
        __syncthreads();

        // ---- S1: x1 rows l0-1, l0
        float4 ov0 = z, ov1 = z, bnew0 = z, bnew1 = z;
        if (i <= 10) {
            {
                const int j = l0 - 1;
                float lw = xhi[j & 7][tm], rx = xlo[j & 7][tp];
                float4 bv = SAME_XB ? xm1 : b_in[cb + (size_t)clampr(j)*W4];
                bnew0 = bv;
                ov0 = stage(j, xm1, xm2, xv0, lw, rx, bv, ta);
                ylo[j & 7][t] = ov0.x;  yhi[j & 7][t] = ov0.w;
            }
            {
                const int j = l0;
                float lw = xhi[j & 7][tm], rx = xlo[j & 7][tp];
                float4 bv = SAME_XB ? xv0 : b_in[cb + (size_t)clampr(j)*W4];
                bnew1 = bv;
                ov1 = stage(j, xv0, xm1, xv1, lw, rx, bv, ta);
                ylo[j & 7][t] = ov1.x;  yhi[j & 7][t] = ov1.w;
            }
        }

        // ---- S2: x2 rows l0-3, l0-2
        float4 pv0 = z, pv1 = z;
        if (i >= 2) {
            {
                const int j = l0 - 3;
                float lw = yhi[j & 7][tm], rx = ylo[j & 7][tp];
                pv0 = stage(j, y1, y2, y0, lw, rx, bf1, tb);
                plo[j & 7][t] = pv0.x;  phi[j & 7][t] = pv0.w;
            }
            {
                const int j = l0 - 2;
                float lw = yhi[j & 7][tm], rx = ylo[j & 7][tp];
                pv1 = stage(j, y0, y1, ov0, lw, rx, bf0, tb);
                plo[j & 7][t] = pv1.x;  phi[j & 7][t] = pv1.w;
            }
        }

        // ---- S3: x3 rows l0-5, l0-4 (always real rows when i >= 4)
        if (i >= 4) {
            {
                const int j = l0 - 5;
                float lw = phi[j & 7][tm], rx = plo[j & 7][tp];
                float4 bv = b_in[cb + (size_t)j*W4];
                float4 on = stage(j, zz1, zz2, zz0, lw, rx, bv, tc);
                x_out[cb + (size_t)j*W4] = on;
            }
            {
                const int j = l0 - 4;
                float lw = phi[j & 7][tm], rx = plo[j & 7][tp];
                float4 bv = b_in[cb + (size_t)j*W4];
                float4 on = stage(j, zz0, zz1, pv0, lw, rx, bv, tc);
                x_out[cb + (size_t)j*W4] = on;
            }
        }

        // ---- FIFO shifts by 2 (renamed away by the x4 unroll)
        zz2 = zz0; zz1 = pv0; zz0 = pv1;
        y2  = y0;  y1  = ov0; y0  = ov1;
        bf1 = bnew0; bf0 = bnew1;
        xm2 = xv0;  xm1 = xv1;
    }
}

// -------------------- launch --------------------
extern "C" void kernel_launch(void* const* d_in, const int* in_sizes, int n_in,
                              void* d_out, int out_size)
{
    const float4* ae  = (const float4*)d_in[0];   // (B,D,H,W) fp32
    const float*  wxy = (const float*)d_in[1];    // (B,2,H,W)
    float4* out = (float4*)d_out;                 // (B,D,H,W)

    float4* xb;
    cudaGetSymbolAddress((void**)&xb, g_x);
    float4* xA = xb;
    float4* xB = xb + NV4;

    // 12 Chebyshev roots on [1,9]: a_k = 5 - 4 cos((2k+1)pi/24).
    // Same extreme-paired sequence as R8..R15 (identical arithmetic).
    double a[12];
    for (int k = 0; k < 12; ++k)
        a[k] = 5.0 - 4.0 * cos((2.0*k + 1.0) * M_PI / 24.0);
    const int ord[12] = {0,11, 1,10, 2,9, 3,8, 4,7, 5,6};
    float tau[12];
    for (int s = 0; s < 12; ++s) tau[s] = (float)(1.0 / a[ord[s]]);

    const int GRID = BB * NCHUNK * 4;   // 512 blocks x 160 threads -> ~4/SM

    rich_tri2<1><<<GRID, NT>>>(ae, ae, wxy, xA, tau[0], tau[1], tau[2]);
    rich_tri2<0><<<GRID, NT>>>(xA, ae, wxy, xB, tau[3], tau[4], tau[5]);
    rich_tri2<0><<<GRID, NT>>>(xB, ae, wxy, xA, tau[6], tau[7], tau[8]);
    rich_tri2<0><<<GRID, NT>>>(xA, ae, wxy, out, tau[9], tau[10], tau[11]);
}